// round 4
// baseline (speedup 1.0000x reference)
#include <cuda_runtime.h>
#include <math.h>

#define NU 100000
#define NTOT 150000
#define DD 64
#define EE 1250000
#define SS 400000
#define TAU 0.2f
#define EDGE_BIAS 0.5f
#define SCAN_B 586   // ceil(NTOT/256)

typedef unsigned long long ull;

// ---- static scratch (no allocations allowed) ----
__device__ float  g_ego[NTOT * DD];        // 38.4 MB
__device__ float  g_l1[NTOT * 2 * DD];     // 76.8 MB  [row][0:64]=orig, [64:128]=masked
__device__ float  g_l2[NTOT * 2 * DD];     // 76.8 MB
__device__ float  g_masked[EE];
__device__ float4 g_csr[EE];               // {col(bits), val, mval, unused} 20 MB
__device__ int    g_counts[NTOT];
__device__ int    g_fillpos[NTOT];
__device__ int    g_rowptr[NTOT + 1];
__device__ int    g_bsum[1024];
__device__ int    g_lastS[EE];
__device__ double g_gate_sum;

// ------------------------------------------------------------------
// 1) zero/init pass
// ------------------------------------------------------------------
__global__ void k_init(const float* __restrict__ vals) {
    int i = blockIdx.x * blockDim.x + threadIdx.x;
    if (i < EE) { g_masked[i] = vals[i]; g_lastS[i] = 0; }
    if (i < NTOT) { g_counts[i] = 0; g_fillpos[i] = 0; }
    if (i == 0) g_gate_sum = 0.0;
}

// ------------------------------------------------------------------
// 2) combined: ego copy (all i), degree count (i<EE), lastS (i<SS)
// ------------------------------------------------------------------
__global__ void k_prep(const float* __restrict__ user,
                       const float* __restrict__ item,
                       const int* __restrict__ rows,
                       const int* __restrict__ sidx) {
    int i = blockIdx.x * blockDim.x + threadIdx.x;
    if (i < NTOT * DD)
        g_ego[i] = (i < NU * DD) ? user[i] : item[i - NU * DD];
    if (i < EE) atomicAdd(&g_counts[rows[i]], 1);
    if (i < SS) atomicMax(&g_lastS[sidx[i]], i);
}

// ------------------------------------------------------------------
// 3) gate MLP as block GEMM, packed f32x2 FMA, LDS.128 A loads.
//    128 edges/block, 256 threads. tx -> 4 hidden cols, ty -> 8 edges.
// ------------------------------------------------------------------
#define TE 128
#define CAT_STRIDE 132
#define GATE_SMEM ((TE * CAT_STRIDE + 128 * 64) * 4)

__device__ __forceinline__ ull dup2(float v) {
    ull r; unsigned int u = __float_as_uint(v);
    asm("mov.b64 %0, {%1, %1};" : "=l"(r) : "r"(u));
    return r;
}
__device__ __forceinline__ void ffma2(ull& acc, ull a, ull b) {
    asm("fma.rn.f32x2 %0, %1, %2, %0;" : "+l"(acc) : "l"(a), "l"(b));
}

__global__ void __launch_bounds__(256, 2)
k_gate_gemm(const int* __restrict__ rows, const int* __restrict__ cols,
            const float* __restrict__ vals, const int* __restrict__ sidx,
            const float* __restrict__ eps,
            const float* __restrict__ W1, const float* __restrict__ b1,
            const float* __restrict__ W2, const float* __restrict__ b2) {
    extern __shared__ float sm[];
    float* catS = sm;                    // [128 edges][132]
    float* Bs   = sm + TE * CAT_STRIDE;  // [128 k][64 hidden]
    __shared__ float b1s[64], W2s[64];
    __shared__ int   eidx[TE];
    __shared__ double gpart[16];

    const int tid  = threadIdx.x;
    const int base = blockIdx.x * TE;

    for (int i = tid; i < 128 * 64 / 4; i += 256)
        ((float4*)Bs)[i] = ((const float4*)W1)[i];
    if (tid < 64) { b1s[tid] = b1[tid]; W2s[tid] = W2[tid]; }

    // stage cat = [ego[su] | ego[sv]] : 2 threads per edge
    {
        int e = tid >> 1, p = tid & 1;
        int s = base + e;
        int idx = __ldg(&sidx[s]);
        if (p == 0) eidx[e] = idx;
        int node = p ? __ldg(&cols[idx]) : __ldg(&rows[idx]);
        const float4* src = (const float4*)(g_ego + node * DD);
        float4* dst = (float4*)(catS + e * CAT_STRIDE + p * DD);
#pragma unroll
        for (int j = 0; j < 16; j++) dst[j] = src[j];
    }
    __syncthreads();

    const int tx = tid & 15, ty = tid >> 4;
    ull acc[8][2];
#pragma unroll
    for (int r = 0; r < 8; r++) { acc[r][0] = 0ull; acc[r][1] = 0ull; }

    const float* abase = catS + ty * 8 * CAT_STRIDE;
    const float* bcol  = Bs + tx * 4;

#pragma unroll 2
    for (int k4 = 0; k4 < 128; k4 += 4) {
        ull B[4][2];
#pragma unroll
        for (int kk = 0; kk < 4; kk++) {
            B[kk][0] = *(const ull*)(bcol + (k4 + kk) * 64);
            B[kk][1] = *(const ull*)(bcol + (k4 + kk) * 64 + 2);
        }
#pragma unroll
        for (int r = 0; r < 8; r++) {
            float4 a = *(const float4*)(abase + r * CAT_STRIDE + k4);
            ull A0 = dup2(a.x), A1 = dup2(a.y), A2 = dup2(a.z), A3 = dup2(a.w);
            ffma2(acc[r][0], A0, B[0][0]); ffma2(acc[r][1], A0, B[0][1]);
            ffma2(acc[r][0], A1, B[1][0]); ffma2(acc[r][1], A1, B[1][1]);
            ffma2(acc[r][0], A2, B[2][0]); ffma2(acc[r][1], A2, B[2][1]);
            ffma2(acc[r][0], A3, B[3][0]); ffma2(acc[r][1], A3, B[3][1]);
        }
    }

    // epilogue: per edge logit = relu(C + b1) @ W2 + b2
    float part[8];
#pragma unroll
    for (int r = 0; r < 8; r++) {
        float p = 0.f;
#pragma unroll
        for (int cp = 0; cp < 2; cp++) {
            unsigned int lo_u, hi_u;
            asm("mov.b64 {%0, %1}, %2;" : "=r"(lo_u), "=r"(hi_u) : "l"(acc[r][cp]));
            int h0 = (tx << 2) + (cp << 1);
            float v0 = fmaxf(__uint_as_float(lo_u) + b1s[h0], 0.f);
            float v1 = fmaxf(__uint_as_float(hi_u) + b1s[h0 + 1], 0.f);
            p = fmaf(v0, W2s[h0], p);
            p = fmaf(v1, W2s[h0 + 1], p);
        }
        part[r] = p;
    }
#pragma unroll
    for (int off = 8; off; off >>= 1)
#pragma unroll
        for (int r = 0; r < 8; r++)
            part[r] += __shfl_xor_sync(0xffffffffu, part[r], off);

    if (tx == 0) {
        float b2v = __ldg(b2);
        double lsum = 0.0;
#pragma unroll
        for (int r = 0; r < 8; r++) {
            int e = ty * 8 + r;
            int s = base + e;
            float logit = part[r] + b2v;
            float ee = eps[s] * (1.f - 2e-6f) + 1e-6f;
            float gumbel = logf(ee) - log1pf(-ee);
            float gate = 1.f / (1.f + expf(-(logit + gumbel) / TAU)) + EDGE_BIAS;
            lsum += (double)gate;
            int idx = eidx[e];
            if (g_lastS[idx] == s) g_masked[idx] = vals[idx] * gate;
        }
        gpart[ty] = lsum;
    }
    __syncthreads();
    if (tid == 0) {
        double t = 0.0;
#pragma unroll
        for (int i = 0; i < 16; i++) t += gpart[i];
        atomicAdd(&g_gate_sum, t);
    }
}

// ------------------------------------------------------------------
// 4) CSR scan (3-phase) + fill
// ------------------------------------------------------------------
__global__ void k_scan1() {
    __shared__ int sh[256];
    int i = blockIdx.x * 256 + threadIdx.x;
    int v = (i < NTOT) ? g_counts[i] : 0;
    sh[threadIdx.x] = v;
    __syncthreads();
    for (int off = 128; off; off >>= 1) {
        if (threadIdx.x < off) sh[threadIdx.x] += sh[threadIdx.x + off];
        __syncthreads();
    }
    if (threadIdx.x == 0) g_bsum[blockIdx.x] = sh[0];
}

__global__ void k_scan2() {
    __shared__ int sh[1024];
    int t = threadIdx.x;
    int v = (t < SCAN_B) ? g_bsum[t] : 0;
    sh[t] = v;
    __syncthreads();
    for (int off = 1; off < 1024; off <<= 1) {
        int u = (t >= off) ? sh[t - off] : 0;
        __syncthreads();
        sh[t] += u;
        __syncthreads();
    }
    if (t < SCAN_B) g_bsum[t] = sh[t] - v;  // exclusive
}

__global__ void k_scan3() {
    __shared__ int sh[256];
    int i = blockIdx.x * 256 + threadIdx.x;
    int v = (i < NTOT) ? g_counts[i] : 0;
    sh[threadIdx.x] = v;
    __syncthreads();
    for (int off = 1; off < 256; off <<= 1) {
        int u = (threadIdx.x >= off) ? sh[threadIdx.x - off] : 0;
        __syncthreads();
        sh[threadIdx.x] += u;
        __syncthreads();
    }
    if (i < NTOT) g_rowptr[i] = g_bsum[blockIdx.x] + sh[threadIdx.x] - v;
    if (i == 0) g_rowptr[NTOT] = EE;
}

__global__ void k_fill(const int* __restrict__ rows, const int* __restrict__ cols,
                       const float* __restrict__ vals) {
    int e = blockIdx.x * blockDim.x + threadIdx.x;
    if (e >= EE) return;
    int r = rows[e];
    int slot = g_rowptr[r] + atomicAdd(&g_fillpos[r], 1);
    float4 rec;
    rec.x = __int_as_float(cols[e]);
    rec.y = vals[e];
    rec.z = g_masked[e];
    rec.w = 0.f;
    g_csr[slot] = rec;
}

// ------------------------------------------------------------------
// 5) SPMM layer 1: both chains gather ego once -> interleaved l1
// ------------------------------------------------------------------
__device__ __forceinline__ void fma2v(float2& a, float v, float2 x) {
    a.x = fmaf(v, x.x, a.x); a.y = fmaf(v, x.y, a.y);
}

__global__ void k_spmm_l1() {
    int warp = (blockIdx.x * blockDim.x + threadIdx.x) >> 5;
    int lane = threadIdx.x & 31;
    if (warp >= NTOT) return;
    int s0 = __ldg(&g_rowptr[warp]);
    int s1 = __ldg(&g_rowptr[warp + 1]);
    const float2* X = (const float2*)g_ego;
    float2 aa = make_float2(0.f, 0.f), ab = make_float2(0.f, 0.f);
    int s = s0;
    for (; s + 4 <= s1; s += 4) {
        float4 e0 = __ldg(&g_csr[s]),     e1 = __ldg(&g_csr[s + 1]);
        float4 e2 = __ldg(&g_csr[s + 2]), e3 = __ldg(&g_csr[s + 3]);
        float2 x0 = __ldg(&X[__float_as_int(e0.x) * 32 + lane]);
        float2 x1 = __ldg(&X[__float_as_int(e1.x) * 32 + lane]);
        float2 x2 = __ldg(&X[__float_as_int(e2.x) * 32 + lane]);
        float2 x3 = __ldg(&X[__float_as_int(e3.x) * 32 + lane]);
        fma2v(aa, e0.y, x0); fma2v(ab, e0.z, x0);
        fma2v(aa, e1.y, x1); fma2v(ab, e1.z, x1);
        fma2v(aa, e2.y, x2); fma2v(ab, e2.z, x2);
        fma2v(aa, e3.y, x3); fma2v(ab, e3.z, x3);
    }
    for (; s < s1; s++) {
        float4 e = __ldg(&g_csr[s]);
        float2 x = __ldg(&X[__float_as_int(e.x) * 32 + lane]);
        fma2v(aa, e.y, x); fma2v(ab, e.z, x);
    }
    float2* L1 = (float2*)g_l1;
    L1[warp * 64 + lane] = aa;
    L1[warp * 64 + 32 + lane] = ab;
}

// ------------------------------------------------------------------
// 6) SPMM layers 2: interleaved l1 -> interleaved l2
// ------------------------------------------------------------------
__global__ void k_spmm_l2() {
    int warp = (blockIdx.x * blockDim.x + threadIdx.x) >> 5;
    int lane = threadIdx.x & 31;
    if (warp >= NTOT) return;
    int s0 = __ldg(&g_rowptr[warp]);
    int s1 = __ldg(&g_rowptr[warp + 1]);
    const float2* X = (const float2*)g_l1;
    float2 aa = make_float2(0.f, 0.f), ab = make_float2(0.f, 0.f);
    int s = s0;
    for (; s + 2 <= s1; s += 2) {
        float4 e0 = __ldg(&g_csr[s]), e1 = __ldg(&g_csr[s + 1]);
        int c0 = __float_as_int(e0.x), c1 = __float_as_int(e1.x);
        float2 xa0 = __ldg(&X[c0 * 64 + lane]);
        float2 xb0 = __ldg(&X[c0 * 64 + 32 + lane]);
        float2 xa1 = __ldg(&X[c1 * 64 + lane]);
        float2 xb1 = __ldg(&X[c1 * 64 + 32 + lane]);
        fma2v(aa, e0.y, xa0); fma2v(ab, e0.z, xb0);
        fma2v(aa, e1.y, xa1); fma2v(ab, e1.z, xb1);
    }
    for (; s < s1; s++) {
        float4 e = __ldg(&g_csr[s]);
        int c = __float_as_int(e.x);
        float2 xa = __ldg(&X[c * 64 + lane]);
        float2 xb = __ldg(&X[c * 64 + 32 + lane]);
        fma2v(aa, e.y, xa); fma2v(ab, e.z, xb);
    }
    float2* L2 = (float2*)g_l2;
    L2[warp * 64 + lane] = aa;
    L2[warp * 64 + 32 + lane] = ab;
}

// ------------------------------------------------------------------
// 7) SPMM layer 3 fused with mean: out = (ego + l1 + l2 + l3) / 4
// ------------------------------------------------------------------
__global__ void k_spmm_l3(float* __restrict__ out) {
    int warp = (blockIdx.x * blockDim.x + threadIdx.x) >> 5;
    int lane = threadIdx.x & 31;
    if (warp >= NTOT) return;
    int s0 = __ldg(&g_rowptr[warp]);
    int s1 = __ldg(&g_rowptr[warp + 1]);
    const float2* X = (const float2*)g_l2;
    float2 aa = make_float2(0.f, 0.f), ab = make_float2(0.f, 0.f);
    int s = s0;
    for (; s + 2 <= s1; s += 2) {
        float4 e0 = __ldg(&g_csr[s]), e1 = __ldg(&g_csr[s + 1]);
        int c0 = __float_as_int(e0.x), c1 = __float_as_int(e1.x);
        float2 xa0 = __ldg(&X[c0 * 64 + lane]);
        float2 xb0 = __ldg(&X[c0 * 64 + 32 + lane]);
        float2 xa1 = __ldg(&X[c1 * 64 + lane]);
        float2 xb1 = __ldg(&X[c1 * 64 + 32 + lane]);
        fma2v(aa, e0.y, xa0); fma2v(ab, e0.z, xb0);
        fma2v(aa, e1.y, xa1); fma2v(ab, e1.z, xb1);
    }
    for (; s < s1; s++) {
        float4 e = __ldg(&g_csr[s]);
        int c = __float_as_int(e.x);
        float2 xa = __ldg(&X[c * 64 + lane]);
        float2 xb = __ldg(&X[c * 64 + 32 + lane]);
        fma2v(aa, e.y, xa); fma2v(ab, e.z, xb);
    }
    const float2* E  = (const float2*)g_ego;
    const float2* L1 = (const float2*)g_l1;
    const float2* L2 = (const float2*)g_l2;
    float2 e  = E[warp * 32 + lane];
    float2 p1 = L1[warp * 64 + lane];
    float2 q1 = L1[warp * 64 + 32 + lane];
    float2 p2 = L2[warp * 64 + lane];
    float2 q2 = L2[warp * 64 + 32 + lane];
    float2* outA = (float2*)out;
    float2* outB = (float2*)out + NTOT * 32;
    outA[warp * 32 + lane] = make_float2((e.x + p1.x + p2.x + aa.x) * 0.25f,
                                         (e.y + p1.y + p2.y + aa.y) * 0.25f);
    outB[warp * 32 + lane] = make_float2((e.x + q1.x + q2.x + ab.x) * 0.25f,
                                         (e.y + q1.y + q2.y + ab.y) * 0.25f);
}

// ------------------------------------------------------------------
// 8) gate mean
// ------------------------------------------------------------------
__global__ void k_final(float* __restrict__ out) {
    out[2 * NTOT * DD] = (float)(g_gate_sum / (double)SS);
}

extern "C" void kernel_launch(void* const* d_in, const int* in_sizes, int n_in,
                              void* d_out, int out_size) {
    const float* user = (const float*)d_in[0];
    const float* item = (const float*)d_in[1];
    const int*   rows = (const int*)d_in[2];
    const int*   cols = (const int*)d_in[3];
    const float* vals = (const float*)d_in[4];
    const int*   sidx = (const int*)d_in[5];
    const float* eps  = (const float*)d_in[6];
    const float* W1   = (const float*)d_in[7];
    const float* b1   = (const float*)d_in[8];
    const float* W2   = (const float*)d_in[9];
    const float* b2   = (const float*)d_in[10];
    float* out = (float*)d_out;

    static int smem_set = 0;
    if (!smem_set) {
        cudaFuncSetAttribute(k_gate_gemm,
                             cudaFuncAttributeMaxDynamicSharedMemorySize, GATE_SMEM);
        smem_set = 1;
    }

    const int TB = 256;
    k_init<<<(EE + TB - 1) / TB, TB>>>(vals);
    k_prep<<<(NTOT * DD + TB - 1) / TB, TB>>>(user, item, rows, sidx);
    k_scan1<<<SCAN_B, 256>>>();
    k_gate_gemm<<<SS / TE, 256, GATE_SMEM>>>(rows, cols, vals, sidx, eps, W1, b1, W2, b2);
    k_scan2<<<1, 1024>>>();
    k_scan3<<<SCAN_B, 256>>>();
    k_fill<<<(EE + TB - 1) / TB, TB>>>(rows, cols, vals);

    const int SPMM_BLOCKS = (NTOT * 32 + TB - 1) / TB;
    k_spmm_l1<<<SPMM_BLOCKS, TB>>>();
    k_spmm_l2<<<SPMM_BLOCKS, TB>>>();
    k_spmm_l3<<<SPMM_BLOCKS, TB>>>(out);

    k_final<<<1, 1>>>(out);
}

// round 6
// speedup vs baseline: 1.2540x; 1.2540x over previous
#include <cuda_runtime.h>
#include <cuda_bf16.h>
#include <math.h>
#include <cstdint>

#define NU 100000
#define NTOT 150000
#define DD 64
#define EE 1250000
#define SS 400000
#define TAU 0.2f
#define EDGE_BIAS 0.5f
#define SCAN_B 586   // ceil(NTOT/256)

typedef unsigned long long ull;

// ---- static scratch (no allocations allowed) ----
__device__ float  g_ego[NTOT * DD];
__device__ float  g_l1[NTOT * 2 * DD];
__device__ float  g_l2[NTOT * 2 * DD];
__device__ float  g_masked[EE];
__device__ int    g_csr_col[EE];
__device__ float2 g_csr_vals2[EE];
__device__ int    g_counts[NTOT];
__device__ int    g_fillpos[NTOT];
__device__ int    g_rowptr[NTOT + 1];
__device__ int    g_bsum[1024];
__device__ int    g_lastS[EE];
__device__ double g_gate_sum;

// ================= helpers =================
__device__ __forceinline__ uint32_t smem_u32(const void* p) {
    uint32_t a;
    asm("{ .reg .u64 t; cvta.to.shared.u64 t, %1; cvt.u32.u64 %0, t; }" : "=r"(a) : "l"(p));
    return a;
}
__device__ __forceinline__ uint32_t pack_bf16x2(float lo, float hi) {
    uint32_t r;
    asm("cvt.rn.bf16x2.f32 %0, %1, %2;" : "=r"(r) : "f"(hi), "f"(lo));
    return r;
}
__device__ __forceinline__ void ldsm_x4(uint32_t (&r)[4], uint32_t addr) {
    asm volatile("ldmatrix.sync.aligned.m8n8.x4.shared.b16 {%0,%1,%2,%3}, [%4];"
        : "=r"(r[0]), "=r"(r[1]), "=r"(r[2]), "=r"(r[3]) : "r"(addr));
}
__device__ __forceinline__ void ldsm_x2t(uint32_t (&r)[2], uint32_t addr) {
    asm volatile("ldmatrix.sync.aligned.m8n8.x2.trans.shared.b16 {%0,%1}, [%2];"
        : "=r"(r[0]), "=r"(r[1]) : "r"(addr));
}
__device__ __forceinline__ void mma_bf16(float (&c)[4], const uint32_t (&a)[4],
                                         const uint32_t (&b)[2]) {
    asm volatile(
        "mma.sync.aligned.m16n8k16.row.col.f32.bf16.bf16.f32 "
        "{%0,%1,%2,%3}, {%4,%5,%6,%7}, {%8,%9}, {%0,%1,%2,%3};"
        : "+f"(c[0]), "+f"(c[1]), "+f"(c[2]), "+f"(c[3])
        : "r"(a[0]), "r"(a[1]), "r"(a[2]), "r"(a[3]), "r"(b[0]), "r"(b[1]));
}

// ------------------------------------------------------------------
// 1) per-edge init
// ------------------------------------------------------------------
__global__ void k_init_edges(const float* __restrict__ vals) {
    int i = blockIdx.x * blockDim.x + threadIdx.x;
    if (i < EE) { g_masked[i] = vals[i]; g_lastS[i] = 0; }
    if (i < NTOT) { g_counts[i] = 0; g_fillpos[i] = 0; }
    if (i == 0) g_gate_sum = 0.0;
}

// ------------------------------------------------------------------
// 2) ego = concat(user, item)
// ------------------------------------------------------------------
__global__ void k_init_ego(const float* __restrict__ user,
                           const float* __restrict__ item) {
    int i = blockIdx.x * blockDim.x + threadIdx.x;
    if (i >= NTOT * DD) return;
    g_ego[i] = (i < NU * DD) ? user[i] : item[i - NU * DD];
}

// ------------------------------------------------------------------
// 3) last-writer-wins marker
// ------------------------------------------------------------------
__global__ void k_lastS(const int* __restrict__ sidx) {
    int s = blockIdx.x * blockDim.x + threadIdx.x;
    if (s >= SS) return;
    atomicMax(&g_lastS[sidx[s]], s);
}

// ------------------------------------------------------------------
// 4) gate MLP via bf16 mma.sync with 2-way float-split emulation.
//    Block = 128 edges, 256 threads (8 warps, warp w -> edge rows 16w..16w+15).
//    A[128e][128k] hi/lo bf16 (stride 136), B[128k][64h] hi/lo (stride 72).
//    C = A1B1 + A1B2 + A2B1 in fp32 mma fragments.
// ------------------------------------------------------------------
#define TE 128
#define A_STRIDE 136
#define B_STRIDE 72
#define A_TILE_B (128 * A_STRIDE * 2)              // 34816
#define B_TILE_B (128 * B_STRIDE * 2)              // 18432
#define GATE_DYN (2 * A_TILE_B + 2 * B_TILE_B)     // 106496

__global__ void __launch_bounds__(256)
k_gate_mma(const int* __restrict__ rows, const int* __restrict__ cols,
           const float* __restrict__ vals, const int* __restrict__ sidx,
           const float* __restrict__ eps,
           const float* __restrict__ W1, const float* __restrict__ b1,
           const float* __restrict__ W2, const float* __restrict__ b2) {
    extern __shared__ char dsm[];
    const uint32_t A1 = smem_u32(dsm);
    const uint32_t A2 = A1 + A_TILE_B;
    const uint32_t B1 = A1 + 2 * A_TILE_B;
    const uint32_t B2 = B1 + B_TILE_B;

    __shared__ float  b1s[64], W2s[64];
    __shared__ int    eidx[TE];
    __shared__ double gpart[8];

    const int tid  = threadIdx.x;
    const int wid  = tid >> 5;
    const int lane = tid & 31;
    const int base = blockIdx.x * TE;

    if (tid < 64) { b1s[tid] = b1[tid]; W2s[tid] = W2[tid]; }

    // ---- stage B = W1 [128k][64h] split hi/lo, 2 cols per thread ----
    for (int i = tid; i < 4096; i += 256) {
        int k = i >> 5, nn = (i & 31) * 2;
        float v0 = __ldg(&W1[k * 64 + nn]);
        float v1 = __ldg(&W1[k * 64 + nn + 1]);
        float h0 = __bfloat162float(__float2bfloat16(v0));
        float h1 = __bfloat162float(__float2bfloat16(v1));
        uint32_t off = (uint32_t)(k * B_STRIDE + nn) * 2u;
        *(uint32_t*)(dsm + (B1 - A1) + off) = pack_bf16x2(h0, h1);
        *(uint32_t*)(dsm + (B2 - A1) + off) = pack_bf16x2(v0 - h0, v1 - h1);
    }

    // ---- stage A = cat(ego[su], ego[sv]) split hi/lo : 2 threads/edge ----
    {
        int e = tid >> 1, p = tid & 1;
        int s = base + e;
        int idx = __ldg(&sidx[s]);
        if (p == 0) eidx[e] = idx;
        int node = p ? __ldg(&cols[idx]) : __ldg(&rows[idx]);
        const float4* src = (const float4*)(g_ego + node * DD);
        uint32_t rowoff = (uint32_t)(e * A_STRIDE + p * DD) * 2u;
#pragma unroll
        for (int j = 0; j < 16; j++) {
            float4 v = __ldg(&src[j]);
            float h0 = __bfloat162float(__float2bfloat16(v.x));
            float h1 = __bfloat162float(__float2bfloat16(v.y));
            float h2 = __bfloat162float(__float2bfloat16(v.z));
            float h3 = __bfloat162float(__float2bfloat16(v.w));
            uint32_t off = rowoff + (uint32_t)j * 8u;
            *(uint2*)(dsm + off) =
                make_uint2(pack_bf16x2(h0, h1), pack_bf16x2(h2, h3));
            *(uint2*)(dsm + A_TILE_B + off) =
                make_uint2(pack_bf16x2(v.x - h0, v.y - h1), pack_bf16x2(v.z - h2, v.w - h3));
        }
    }
    __syncthreads();

    // ---- mainloop: 8 k-steps, 8 n-tiles, 3 split passes ----
    float C[8][4];
#pragma unroll
    for (int n = 0; n < 8; n++)
#pragma unroll
        for (int q = 0; q < 4; q++) C[n][q] = 0.f;

    const uint32_t a_lane_off =
        (uint32_t)((wid * 16 + (lane & 15)) * A_STRIDE + (lane >> 4) * 8) * 2u;

#pragma unroll
    for (int k = 0; k < 8; k++) {
        uint32_t a1[4], a2[4];
        uint32_t a_addr = A1 + a_lane_off + (uint32_t)(k * 16 * 2);
        ldsm_x4(a1, a_addr);
        ldsm_x4(a2, a_addr + A_TILE_B);
        uint32_t b_row = B1 + (uint32_t)((k * 16 + (lane & 15)) * B_STRIDE) * 2u;
#pragma unroll
        for (int n = 0; n < 8; n++) {
            uint32_t bb1[2], bb2[2];
            uint32_t b_addr = b_row + (uint32_t)(n * 8 * 2);
            ldsm_x2t(bb1, b_addr);
            ldsm_x2t(bb2, b_addr + B_TILE_B);
            mma_bf16(C[n], a1, bb1);
            mma_bf16(C[n], a1, bb2);
            mma_bf16(C[n], a2, bb1);
        }
    }

    // ---- epilogue: logit = relu(C + b1) @ W2 + b2 ----
    const int qr = lane >> 2;        // row in tile (0..7)
    const int qc = (lane & 3) * 2;   // col pair base
    float pl = 0.f, ph = 0.f;
#pragma unroll
    for (int n = 0; n < 8; n++) {
        int c0 = n * 8 + qc, c1 = c0 + 1;
        pl += fmaxf(C[n][0] + b1s[c0], 0.f) * W2s[c0]
            + fmaxf(C[n][1] + b1s[c1], 0.f) * W2s[c1];
        ph += fmaxf(C[n][2] + b1s[c0], 0.f) * W2s[c0]
            + fmaxf(C[n][3] + b1s[c1], 0.f) * W2s[c1];
    }
    pl += __shfl_xor_sync(0xffffffffu, pl, 1);
    pl += __shfl_xor_sync(0xffffffffu, pl, 2);
    ph += __shfl_xor_sync(0xffffffffu, ph, 1);
    ph += __shfl_xor_sync(0xffffffffu, ph, 2);

    double gsum = 0.0;
    if ((lane & 3) == 0) {
        float b2v = __ldg(b2);
        float logit[2] = {pl + b2v, ph + b2v};
#pragma unroll
        for (int h = 0; h < 2; h++) {
            int e = wid * 16 + qr + h * 8;
            int s = base + e;
            float ee = __ldg(&eps[s]) * (1.f - 2e-6f) + 1e-6f;
            float gumbel = logf(ee) - log1pf(-ee);
            float gate = 1.f / (1.f + expf(-(logit[h] + gumbel) / TAU)) + EDGE_BIAS;
            gsum += (double)gate;
            int idx = eidx[e];
            if (g_lastS[idx] == s) g_masked[idx] = vals[idx] * gate;
        }
    }
#pragma unroll
    for (int off = 16; off; off >>= 1)
        gsum += __shfl_xor_sync(0xffffffffu, gsum, off);
    if (lane == 0) gpart[wid] = gsum;
    __syncthreads();
    if (tid == 0) {
        double t = 0.0;
#pragma unroll
        for (int i = 0; i < 8; i++) t += gpart[i];
        atomicAdd(&g_gate_sum, t);
    }
}

// ------------------------------------------------------------------
// 5) CSR build: count + 3-phase scan + fill
// ------------------------------------------------------------------
__global__ void k_count(const int* __restrict__ rows) {
    int e = blockIdx.x * blockDim.x + threadIdx.x;
    if (e >= EE) return;
    atomicAdd(&g_counts[rows[e]], 1);
}

__global__ void k_scan1() {
    __shared__ int sh[256];
    int i = blockIdx.x * 256 + threadIdx.x;
    int v = (i < NTOT) ? g_counts[i] : 0;
    sh[threadIdx.x] = v;
    __syncthreads();
    for (int off = 128; off; off >>= 1) {
        if (threadIdx.x < off) sh[threadIdx.x] += sh[threadIdx.x + off];
        __syncthreads();
    }
    if (threadIdx.x == 0) g_bsum[blockIdx.x] = sh[0];
}

__global__ void k_scan2() {
    __shared__ int sh[1024];
    int t = threadIdx.x;
    int v = (t < SCAN_B) ? g_bsum[t] : 0;
    sh[t] = v;
    __syncthreads();
    for (int off = 1; off < 1024; off <<= 1) {
        int u = (t >= off) ? sh[t - off] : 0;
        __syncthreads();
        sh[t] += u;
        __syncthreads();
    }
    if (t < SCAN_B) g_bsum[t] = sh[t] - v;  // exclusive
}

__global__ void k_scan3() {
    __shared__ int sh[256];
    int i = blockIdx.x * 256 + threadIdx.x;
    int v = (i < NTOT) ? g_counts[i] : 0;
    sh[threadIdx.x] = v;
    __syncthreads();
    for (int off = 1; off < 256; off <<= 1) {
        int u = (threadIdx.x >= off) ? sh[threadIdx.x - off] : 0;
        __syncthreads();
        sh[threadIdx.x] += u;
        __syncthreads();
    }
    if (i < NTOT) g_rowptr[i] = g_bsum[blockIdx.x] + sh[threadIdx.x] - v;
    if (i == 0) g_rowptr[NTOT] = EE;
}

__global__ void k_fill(const int* __restrict__ rows, const int* __restrict__ cols,
                       const float* __restrict__ vals) {
    int e = blockIdx.x * blockDim.x + threadIdx.x;
    if (e >= EE) return;
    int r = rows[e];
    int slot = g_rowptr[r] + atomicAdd(&g_fillpos[r], 1);
    g_csr_col[slot] = cols[e];
    g_csr_vals2[slot] = make_float2(vals[e], g_masked[e]);
}

// ------------------------------------------------------------------
// 6) SPMM layer 1
// ------------------------------------------------------------------
__device__ __forceinline__ void fma2v(float2& a, float v, float2 x) {
    a.x = fmaf(v, x.x, a.x); a.y = fmaf(v, x.y, a.y);
}

__global__ void k_spmm_l1() {
    int warp = (blockIdx.x * blockDim.x + threadIdx.x) >> 5;
    int lane = threadIdx.x & 31;
    if (warp >= NTOT) return;
    int s0 = __ldg(&g_rowptr[warp]);
    int s1 = __ldg(&g_rowptr[warp + 1]);
    const float2* X = (const float2*)g_ego;
    float2 aa = make_float2(0.f, 0.f), ab = make_float2(0.f, 0.f);
    int s = s0;
    for (; s + 4 <= s1; s += 4) {
        int c0 = __ldg(&g_csr_col[s]),     c1 = __ldg(&g_csr_col[s + 1]);
        int c2 = __ldg(&g_csr_col[s + 2]), c3 = __ldg(&g_csr_col[s + 3]);
        float2 v0 = __ldg(&g_csr_vals2[s]),     v1 = __ldg(&g_csr_vals2[s + 1]);
        float2 v2 = __ldg(&g_csr_vals2[s + 2]), v3 = __ldg(&g_csr_vals2[s + 3]);
        float2 x0 = __ldg(&X[c0 * 32 + lane]);
        float2 x1 = __ldg(&X[c1 * 32 + lane]);
        float2 x2 = __ldg(&X[c2 * 32 + lane]);
        float2 x3 = __ldg(&X[c3 * 32 + lane]);
        fma2v(aa, v0.x, x0); fma2v(ab, v0.y, x0);
        fma2v(aa, v1.x, x1); fma2v(ab, v1.y, x1);
        fma2v(aa, v2.x, x2); fma2v(ab, v2.y, x2);
        fma2v(aa, v3.x, x3); fma2v(ab, v3.y, x3);
    }
    for (; s < s1; s++) {
        int c = __ldg(&g_csr_col[s]);
        float2 v = __ldg(&g_csr_vals2[s]);
        float2 x = __ldg(&X[c * 32 + lane]);
        fma2v(aa, v.x, x); fma2v(ab, v.y, x);
    }
    float2* L1 = (float2*)g_l1;
    L1[warp * 64 + lane] = aa;
    L1[warp * 64 + 32 + lane] = ab;
}

// ------------------------------------------------------------------
// 7) SPMM layer 2
// ------------------------------------------------------------------
__global__ void k_spmm_l2() {
    int warp = (blockIdx.x * blockDim.x + threadIdx.x) >> 5;
    int lane = threadIdx.x & 31;
    if (warp >= NTOT) return;
    int s0 = __ldg(&g_rowptr[warp]);
    int s1 = __ldg(&g_rowptr[warp + 1]);
    const float2* X = (const float2*)g_l1;
    float2 aa = make_float2(0.f, 0.f), ab = make_float2(0.f, 0.f);
    int s = s0;
    for (; s + 2 <= s1; s += 2) {
        int c0 = __ldg(&g_csr_col[s]), c1 = __ldg(&g_csr_col[s + 1]);
        float2 v0 = __ldg(&g_csr_vals2[s]), v1 = __ldg(&g_csr_vals2[s + 1]);
        float2 xa0 = __ldg(&X[c0 * 64 + lane]);
        float2 xb0 = __ldg(&X[c0 * 64 + 32 + lane]);
        float2 xa1 = __ldg(&X[c1 * 64 + lane]);
        float2 xb1 = __ldg(&X[c1 * 64 + 32 + lane]);
        fma2v(aa, v0.x, xa0); fma2v(ab, v0.y, xb0);
        fma2v(aa, v1.x, xa1); fma2v(ab, v1.y, xb1);
    }
    for (; s < s1; s++) {
        int c = __ldg(&g_csr_col[s]);
        float2 v = __ldg(&g_csr_vals2[s]);
        float2 xa = __ldg(&X[c * 64 + lane]);
        float2 xb = __ldg(&X[c * 64 + 32 + lane]);
        fma2v(aa, v.x, xa); fma2v(ab, v.y, xb);
    }
    float2* L2 = (float2*)g_l2;
    L2[warp * 64 + lane] = aa;
    L2[warp * 64 + 32 + lane] = ab;
}

// ------------------------------------------------------------------
// 8) SPMM layer 3 fused with mean
// ------------------------------------------------------------------
__global__ void k_spmm_l3(float* __restrict__ out) {
    int warp = (blockIdx.x * blockDim.x + threadIdx.x) >> 5;
    int lane = threadIdx.x & 31;
    if (warp >= NTOT) return;
    int s0 = __ldg(&g_rowptr[warp]);
    int s1 = __ldg(&g_rowptr[warp + 1]);
    const float2* X = (const float2*)g_l2;
    float2 aa = make_float2(0.f, 0.f), ab = make_float2(0.f, 0.f);
    int s = s0;
    for (; s + 2 <= s1; s += 2) {
        int c0 = __ldg(&g_csr_col[s]), c1 = __ldg(&g_csr_col[s + 1]);
        float2 v0 = __ldg(&g_csr_vals2[s]), v1 = __ldg(&g_csr_vals2[s + 1]);
        float2 xa0 = __ldg(&X[c0 * 64 + lane]);
        float2 xb0 = __ldg(&X[c0 * 64 + 32 + lane]);
        float2 xa1 = __ldg(&X[c1 * 64 + lane]);
        float2 xb1 = __ldg(&X[c1 * 64 + 32 + lane]);
        fma2v(aa, v0.x, xa0); fma2v(ab, v0.y, xb0);
        fma2v(aa, v1.x, xa1); fma2v(ab, v1.y, xb1);
    }
    for (; s < s1; s++) {
        int c = __ldg(&g_csr_col[s]);
        float2 v = __ldg(&g_csr_vals2[s]);
        float2 xa = __ldg(&X[c * 64 + lane]);
        float2 xb = __ldg(&X[c * 64 + 32 + lane]);
        fma2v(aa, v.x, xa); fma2v(ab, v.y, xb);
    }
    const float2* E  = (const float2*)g_ego;
    const float2* L1 = (const float2*)g_l1;
    const float2* L2 = (const float2*)g_l2;
    float2 e  = E[warp * 32 + lane];
    float2 p1 = L1[warp * 64 + lane];
    float2 q1 = L1[warp * 64 + 32 + lane];
    float2 p2 = L2[warp * 64 + lane];
    float2 q2 = L2[warp * 64 + 32 + lane];
    float2* outA = (float2*)out;
    float2* outB = (float2*)out + NTOT * 32;
    outA[warp * 32 + lane] = make_float2((e.x + p1.x + p2.x + aa.x) * 0.25f,
                                         (e.y + p1.y + p2.y + aa.y) * 0.25f);
    outB[warp * 32 + lane] = make_float2((e.x + q1.x + q2.x + ab.x) * 0.25f,
                                         (e.y + q1.y + q2.y + ab.y) * 0.25f);
}

// ------------------------------------------------------------------
// 9) gate mean
// ------------------------------------------------------------------
__global__ void k_final(float* __restrict__ out) {
    out[2 * NTOT * DD] = (float)(g_gate_sum / (double)SS);
}

extern "C" void kernel_launch(void* const* d_in, const int* in_sizes, int n_in,
                              void* d_out, int out_size) {
    const float* user = (const float*)d_in[0];
    const float* item = (const float*)d_in[1];
    const int*   rows = (const int*)d_in[2];
    const int*   cols = (const int*)d_in[3];
    const float* vals = (const float*)d_in[4];
    const int*   sidx = (const int*)d_in[5];
    const float* eps  = (const float*)d_in[6];
    const float* W1   = (const float*)d_in[7];
    const float* b1   = (const float*)d_in[8];
    const float* W2   = (const float*)d_in[9];
    const float* b2   = (const float*)d_in[10];
    float* out = (float*)d_out;

    static int smem_set = 0;
    if (!smem_set) {
        cudaFuncSetAttribute(k_gate_mma,
                             cudaFuncAttributeMaxDynamicSharedMemorySize, GATE_DYN);
        smem_set = 1;
    }

    const int TB = 256;
    k_init_edges<<<(EE + TB - 1) / TB, TB>>>(vals);
    k_init_ego<<<(NTOT * DD + TB - 1) / TB, TB>>>(user, item);
    k_lastS<<<(SS + TB - 1) / TB, TB>>>(sidx);
    k_gate_mma<<<SS / TE, 256, GATE_DYN>>>(rows, cols, vals, sidx, eps, W1, b1, W2, b2);
    k_count<<<(EE + TB - 1) / TB, TB>>>(rows);
    k_scan1<<<SCAN_B, 256>>>();
    k_scan2<<<1, 1024>>>();
    k_scan3<<<SCAN_B, 256>>>();
    k_fill<<<(EE + TB - 1) / TB, TB>>>(rows, cols, vals);

    const int SPMM_BLOCKS = (NTOT * 32 + TB - 1) / TB;
    k_spmm_l1<<<SPMM_BLOCKS, TB>>>();
    k_spmm_l2<<<SPMM_BLOCKS, TB>>>();
    k_spmm_l3<<<SPMM_BLOCKS, TB>>>(out);

    k_final<<<1, 1>>>(out);
}